// round 12
// baseline (speedup 1.0000x reference)
#include <cuda_runtime.h>
#include <cuda_fp16.h>

#define H    1024
#define HH   1025
#define G3   3075
#define TQ   512
#define TT   4608
#define KP   1088
#define NTHR 256
#define NC   129      // CTAs (fused: each handles q and p for its 16 outputs)
#define OPC  16       // outputs per CTA (2 per warp)

__device__ float  g_gh [(size_t)TT * (2 * G3)];
__device__ float  g_h0 [(size_t)TT * 2050];
__device__ __half g_A16[(size_t)TT * 2 * KP];
__device__ __half g_W16[(size_t)2 * G3 * KP];
__device__ float  g_yfx[TT];
__device__ int    g_bar[4096];

struct TrueT  { static constexpr bool value = true;  };
struct FalseT { static constexpr bool value = false; };

__global__ void zero_bar_kernel() {
    int i = blockIdx.x * blockDim.x + threadIdx.x;
    if (i < 4096) g_bar[i] = 0;
}

__global__ void __launch_bounds__(NTHR) prep_h0_kernel(
    const float* __restrict__ e_q, const float* __restrict__ e_p,
    const float* __restrict__ f_s, const float* __restrict__ f_e)
{
    int t = blockIdx.x, tid = threadIdx.x;
    for (int i = tid; i < 2050; i += NTHR) {
        float v;
        if (t < TQ) v = (i < 2048) ? e_q[(size_t)t * 2048 + i] : 0.f;
        else {
            int pt = t - TQ;
            v = (i < 2048) ? e_p[(size_t)pt * 2048 + i] : (i == 2048 ? f_s[pt] : f_e[pt]);
        }
        g_h0[(size_t)t * 2050 + i] = v;
        int d = (i >= HH) ? 1 : 0;
        g_A16[(size_t)t * (2 * KP) + (size_t)d * KP + (i - d * HH)] = __float2half_rn(v);
    }
    for (int i = tid; i < 2 * (KP - HH); i += NTHR) {
        int d = (i < (KP - HH)) ? 0 : 1;
        int k = HH + (i - d * (KP - HH));
        g_A16[(size_t)t * (2 * KP) + (size_t)d * KP + k] = __float2half_rn(0.f);
    }
}

__global__ void __launch_bounds__(NTHR) prep_whh_kernel(
    const float* __restrict__ Whh_f, const float* __restrict__ Whh_b)
{
    int r = blockIdx.x, d = r / G3, n = r % G3;
    const float* W = d ? Whh_b : Whh_f;
    for (int k = threadIdx.x; k < KP; k += NTHR)
        g_W16[(size_t)r * KP + k] = __float2half_rn(k < HH ? W[(size_t)n * HH + k] : 0.f);
}

__device__ __forceinline__ unsigned smem_u32(const void* p) {
    return (unsigned)__cvta_generic_to_shared(p);
}
__device__ __forceinline__ void ldmx4(unsigned& r0, unsigned& r1, unsigned& r2, unsigned& r3,
                                      unsigned a) {
    asm volatile("ldmatrix.sync.aligned.m8n8.x4.shared.b16 {%0,%1,%2,%3}, [%4];"
                 : "=r"(r0), "=r"(r1), "=r"(r2), "=r"(r3) : "r"(a));
}
__device__ __forceinline__ void mma16816(float* c, const unsigned* a, const unsigned* b) {
    asm volatile("mma.sync.aligned.m16n8k16.row.col.f32.f16.f16.f32 "
                 "{%0,%1,%2,%3},{%4,%5,%6,%7},{%8,%9},{%0,%1,%2,%3};"
                 : "+f"(c[0]), "+f"(c[1]), "+f"(c[2]), "+f"(c[3])
                 : "r"(a[0]), "r"(a[1]), "r"(a[2]), "r"(a[3]), "r"(b[0]), "r"(b[1]));
}

__global__ void __launch_bounds__(NTHR) gh_gemm_kernel(
    const float* __restrict__ bhh_f, const float* __restrict__ bhh_b)
{
    const int d = blockIdx.z, m0 = blockIdx.y * 128, n0 = blockIdx.x * 64;
    __shared__ __half As[128][72];
    __shared__ __half Bs[64][72];
    int tid = threadIdx.x, lane = tid & 31, warp = tid >> 5;
    int wm = warp >> 1, wn = warp & 1;
    float c[2][4][4];
    #pragma unroll
    for (int a = 0; a < 2; a++)
        #pragma unroll
        for (int b = 0; b < 4; b++)
            #pragma unroll
            for (int e = 0; e < 4; e++) c[a][b][e] = 0.f;

    const __half* Bg = g_W16 + (size_t)d * G3 * KP;
    for (int k0 = 0; k0 < KP; k0 += 64) {
        #pragma unroll
        for (int it = 0; it < 4; it++) {
            int idx = it * NTHR + tid, row = idx >> 3, q = idx & 7;
            *(uint4*)&As[row][q * 8] =
                *(const uint4*)(g_A16 + (size_t)(m0 + row) * (2 * KP) + (size_t)d * KP + k0 + q * 8);
        }
        #pragma unroll
        for (int it = 0; it < 2; it++) {
            int idx = it * NTHR + tid, row = idx >> 3, q = idx & 7;
            int n = n0 + row;
            uint4 v = make_uint4(0u, 0u, 0u, 0u);
            if (n < G3) v = *(const uint4*)(Bg + (size_t)n * KP + k0 + q * 8);
            *(uint4*)&Bs[row][q * 8] = v;
        }
        __syncthreads();
        #pragma unroll
        for (int ks = 0; ks < 4; ks++) {
            unsigned a[2][4], b[2][4];
            #pragma unroll
            for (int mf = 0; mf < 2; mf++)
                ldmx4(a[mf][0], a[mf][1], a[mf][2], a[mf][3],
                      smem_u32(&As[wm * 32 + mf * 16 + (lane & 15)][ks * 16 + (lane >> 4) * 8]));
            #pragma unroll
            for (int nf2 = 0; nf2 < 2; nf2++) {
                int grp = lane >> 3, l = lane & 7;
                ldmx4(b[nf2][0], b[nf2][1], b[nf2][2], b[nf2][3],
                      smem_u32(&Bs[wn * 32 + nf2 * 16 + l + (grp >> 1) * 8][ks * 16 + (grp & 1) * 8]));
            }
            #pragma unroll
            for (int mf = 0; mf < 2; mf++)
                #pragma unroll
                for (int nf = 0; nf < 4; nf++) {
                    unsigned bb[2] = { b[nf >> 1][(nf & 1) * 2], b[nf >> 1][(nf & 1) * 2 + 1] };
                    mma16816(c[mf][nf], a[mf], bb);
                }
        }
        __syncthreads();
    }
    const float* bhh = d ? bhh_b : bhh_f;
    #pragma unroll
    for (int mf = 0; mf < 2; mf++)
        #pragma unroll
        for (int nf = 0; nf < 4; nf++) {
            int mrow = m0 + wm * 32 + mf * 16 + (lane >> 2);
            int ncol = n0 + wn * 32 + nf * 8 + (lane & 3) * 2;
            float* p1 = g_gh + (size_t)mrow * (2 * G3) + (size_t)d * G3;
            float* p2 = g_gh + (size_t)(mrow + 8) * (2 * G3) + (size_t)d * G3;
            if (ncol < G3)     { p1[ncol]     = c[mf][nf][0] + bhh[ncol];
                                 p2[ncol]     = c[mf][nf][2] + bhh[ncol]; }
            if (ncol + 1 < G3) { p1[ncol + 1] = c[mf][nf][1] + bhh[ncol + 1];
                                 p2[ncol + 1] = c[mf][nf][3] + bhh[ncol + 1]; }
        }
}

// ---------------- barrier primitives ----------------
__device__ __forceinline__ int ld_acq_gpu(const int* p) {
    int v;
    asm volatile("ld.acquire.gpu.global.s32 %0, [%1];" : "=r"(v) : "l"(p) : "memory");
    return v;
}
__device__ __forceinline__ void red_rel_gpu(int* p) {
    asm volatile("red.release.gpu.global.add.s32 [%0], 1;" :: "l"(p) : "memory");
}
__device__ __forceinline__ void st_rel_cta(int* p, int v) {
    asm volatile("st.release.cta.s32 [%0], %1;" :: "l"(p), "r"(v) : "memory");
}
__device__ __forceinline__ int ld_acq_cta(const int* p) {
    int v;
    asm volatile("ld.acquire.cta.s32 %0, [%1];" : "=r"(v) : "l"(p) : "memory");
    return v;
}

// scan: fused q+p chains, all weights register-resident, 1 CTA/SM
__global__ void __launch_bounds__(NTHR, 1) scan_kernel(
    const float* __restrict__ Wih_f, const float* __restrict__ Wih_b,
    const float* __restrict__ bih_f, const float* __restrict__ bih_b,
    float* __restrict__ out)
{
    __shared__ float bsm[48];
    __shared__ int s_step;

    const int tid = threadIdx.x, lane = tid & 31, warp = tid >> 5;
    const int ostart = blockIdx.x * OPC;

    // ---- stage all 6 weight rows into registers ----
    __half2 wreg[6][16];
    #pragma unroll
    for (int r = 0; r < 6; r++) {
        int o = r / 3, g = r % 3;
        int gidx = ostart + 2 * warp + o; if (gidx > 2048) gidx = 2048;
        int dir = (gidx >= HH) ? 1 : 0, j = gidx - dir * HH;
        const float* src = (dir ? Wih_b : Wih_f) + (size_t)(g * HH + j) * H;
        #pragma unroll
        for (int cc = 0; cc < 4; cc++) {
            int k0 = cc * 256 + lane * 8;
            float4 f0 = *(const float4*)(src + k0);
            float4 f1 = *(const float4*)(src + k0 + 4);
            wreg[r][cc * 4 + 0] = __floats2half2_rn(f0.x, f0.y);
            wreg[r][cc * 4 + 1] = __floats2half2_rn(f0.z, f0.w);
            wreg[r][cc * 4 + 2] = __floats2half2_rn(f1.x, f1.y);
            wreg[r][cc * 4 + 3] = __floats2half2_rn(f1.z, f1.w);
        }
        if (lane == 0) bsm[warp * 6 + r] = (dir ? bih_b : bih_f)[g * HH + j];
    }
    if (tid == 0) s_step = 0;
    __syncthreads();

    const bool gate_lane = (lane == 0 || lane == 16);
    const int gidx_me = ostart + 2 * warp + (lane >> 4);
    const int gclamp = (gidx_me > 2048) ? 2048 : gidx_me;
    const int gdir = (gclamp >= HH) ? 1 : 0;
    const size_t gh_off0 = (size_t)gdir * G3 + (gclamp - gdir * HH);

    auto build_x = [&](__half2* xh, int ptok) {     // ptok = previous token, -1 = zeros
        if (ptok < 0) {
            #pragma unroll
            for (int k2 = 0; k2 < 16; k2++) xh[k2] = __float2half2_rn(0.f);
        } else {
            const float* prev = out + (size_t)ptok * 2048;
            float yfxv = *(volatile float*)&g_yfx[ptok];
            #pragma unroll
            for (int cc = 0; cc < 4; cc++) {
                int k0 = cc * 256 + lane * 8;
                float4 a0 = *(const float4*)(prev + k0);
                float4 a1 = *(const float4*)(prev + k0 + 4);
                float4 c0 = *(const float4*)(prev + 1024 + k0);
                float4 c1 = *(const float4*)(prev + 1024 + k0 + 4);
                float carry = __shfl_up_sync(0xffffffffu, c1.w, 1);
                if (lane == 0) carry = (cc == 0) ? yfxv : prev[1023 + cc * 256];
                xh[cc * 4 + 0] = __floats2half2_rn(a0.x + carry, a0.y + c0.x);
                xh[cc * 4 + 1] = __floats2half2_rn(a0.z + c0.y,  a0.w + c0.z);
                xh[cc * 4 + 2] = __floats2half2_rn(a1.x + c0.w,  a1.y + c1.x);
                xh[cc * 4 + 3] = __floats2half2_rn(a1.z + c1.y,  a1.w + c1.z);
            }
        }
    };

    auto gemv = [&](const __half2* xh, float* rs) {
        #pragma unroll
        for (int r = 0; r < 6; r++) {
            __half2 acc = __float2half2_rn(0.f);
            float fx = 0.f, fy = 0.f;
            #pragma unroll
            for (int cc = 0; cc < 4; cc++) {
                acc = __hfma2(wreg[r][cc * 4 + 0], xh[cc * 4 + 0], acc);
                acc = __hfma2(wreg[r][cc * 4 + 1], xh[cc * 4 + 1], acc);
                acc = __hfma2(wreg[r][cc * 4 + 2], xh[cc * 4 + 2], acc);
                acc = __hfma2(wreg[r][cc * 4 + 3], xh[cc * 4 + 3], acc);
                if (cc & 1) {
                    fx += __low2float(acc); fy += __high2float(acc);
                    acc = __float2half2_rn(0.f);
                }
            }
            rs[r] = fx + fy;
        }
    };

    auto gates = [&](const float* rs, int token,
                     float ghR, float ghZ, float ghN, float hv) {
        if (gate_lane && gidx_me < 2049) {
            float iR = (lane < 16) ? rs[0] : rs[3];
            float iZ = (lane < 16) ? rs[1] : rs[4];
            float iN = (lane < 16) ? rs[2] : rs[5];
            int rb = (lane >> 4) * 3;
            iR += bsm[warp * 6 + rb];
            iZ += bsm[warp * 6 + rb + 1];
            iN += bsm[warp * 6 + rb + 2];
            float rg = 1.f / (1.f + __expf(-(iR + ghR)));
            float zg = 1.f / (1.f + __expf(-(iZ + ghZ)));
            float ng = tanhf(iN + rg * ghN);
            float y = (1.f - zg) * ng + zg * hv;
            if (gidx_me < 1024)       out[(size_t)token * 2048 + gidx_me] = y;
            else if (gidx_me == 1024) g_yfx[token] = y;
            else                      out[(size_t)token * 2048 + gidx_me - 1] = y;
        }
    };

    auto do_step = [&](int i, auto dualc) {
        constexpr bool DUAL = decltype(dualc)::value;
        const int tp = TQ + i;

        float ghRp = 0.f, ghZp = 0.f, ghNp = 0.f, hvp = 0.f;
        float ghRq = 0.f, ghZq = 0.f, ghNq = 0.f, hvq = 0.f;
        if (gate_lane) {
            const float* gp = g_gh + (size_t)tp * (2 * G3) + gh_off0;
            ghRp = gp[0]; ghZp = gp[HH]; ghNp = gp[2 * HH];
            hvp = g_h0[(size_t)tp * 2050 + gclamp];
            if (DUAL) {
                const float* gq = g_gh + (size_t)i * (2 * G3) + gh_off0;
                ghRq = gq[0]; ghZq = gq[HH]; ghNq = gq[2 * HH];
                hvq = g_h0[(size_t)i * 2050 + gclamp];
            }
        }

        if (i > 0) {
            if (warp == 0) {
                while (ld_acq_gpu(&g_bar[i - 1]) < NC) { }
                if (lane == 0) st_rel_cta(&s_step, i);
            } else {
                while (ld_acq_cta(&s_step) < i) { }
            }
        }

        __half2 xp[16];
        build_x(xp, (i > 0) ? (tp - 1) : -1);
        float rsp[6];
        gemv(xp, rsp);

        if (DUAL) {
            __half2 xq[16];
            build_x(xq, i - 1);
            float rsq[6];
            gemv(xq, rsq);
            #pragma unroll
            for (int r = 0; r < 6; r++)
                #pragma unroll
                for (int off = 16; off; off >>= 1) {
                    rsp[r] += __shfl_xor_sync(0xffffffffu, rsp[r], off);
                    rsq[r] += __shfl_xor_sync(0xffffffffu, rsq[r], off);
                }
            gates(rsq, i, ghRq, ghZq, ghNq, hvq);
            gates(rsp, tp, ghRp, ghZp, ghNp, hvp);
        } else {
            #pragma unroll
            for (int r = 0; r < 6; r++)
                #pragma unroll
                for (int off = 16; off; off >>= 1)
                    rsp[r] += __shfl_xor_sync(0xffffffffu, rsp[r], off);
            gates(rsp, tp, ghRp, ghZp, ghNp, hvp);
        }

        __syncthreads();
        if (tid == 0) red_rel_gpu(&g_bar[i]);
    };

    for (int i = 0; i < TQ; i++)        do_step(i, TrueT{});
    for (int i = TQ; i < 4096; i++)     do_step(i, FalseT{});
}

extern "C" void kernel_launch(void* const* d_in, const int* in_sizes, int n_in,
                              void* d_out, int out_size)
{
    const float* e_q   = (const float*)d_in[0];
    const float* e_p   = (const float*)d_in[1];
    const float* f_s   = (const float*)d_in[2];
    const float* f_e   = (const float*)d_in[3];
    const float* Wih_f = (const float*)d_in[4];
    const float* Whh_f = (const float*)d_in[5];
    const float* bih_f = (const float*)d_in[6];
    const float* bhh_f = (const float*)d_in[7];
    const float* Wih_b = (const float*)d_in[8];
    const float* Whh_b = (const float*)d_in[9];
    const float* bih_b = (const float*)d_in[10];
    const float* bhh_b = (const float*)d_in[11];

    zero_bar_kernel<<<16, 256>>>();
    prep_h0_kernel<<<TT, NTHR>>>(e_q, e_p, f_s, f_e);
    prep_whh_kernel<<<2 * G3, NTHR>>>(Whh_f, Whh_b);
    gh_gemm_kernel<<<dim3(49, 36, 2), NTHR>>>(bhh_f, bhh_b);
    scan_kernel<<<NC, NTHR>>>(Wih_f, Wih_b, bih_f, bih_b, (float*)d_out);
}